// round 5
// baseline (speedup 1.0000x reference)
#include <cuda_runtime.h>
#include <math.h>

// Problem constants
#define LL    1024      // seq len
#define DD    1024      // d_model
#define HH    16        // heads
#define DPT   64        // depth per head
#define BS    16        // B*S
#define NTOK  16384     // BS*LL
#define QT    16        // queries per attention block

// Scratch (static device globals; no runtime allocation)
__device__ float g_qp[NTOK * DD];
__device__ float g_kp[NTOK * DD];
__device__ float g_vp[NTOK * DD];
__device__ float g_ctx[NTOK * DD];

// ---------------------------------------------------------------------------
// SGEMM: C[M,1024] = A[M,1024] @ W[1024,1024] + bias, M = 16384
// 128x128 block, BK=8, 256 threads, 8x8 microtile per thread.
// ---------------------------------------------------------------------------
__global__ __launch_bounds__(256) void sgemm_bias_kernel(
    const float* __restrict__ A, const float* __restrict__ W,
    const float* __restrict__ bias, float* __restrict__ C)
{
    __shared__ float As[8][128];
    __shared__ float Bsm[8][128];

    const int tid = threadIdx.x;
    const int tx = tid & 15;        // 0..15  -> col group
    const int ty = tid >> 4;        // 0..15  -> row group
    const int row0 = blockIdx.y * 128;
    const int col0 = blockIdx.x * 128;

    // load mappings
    const int arow = tid >> 1;           // 0..127
    const int acol = (tid & 1) * 4;      // 0 or 4
    const int brow = tid >> 5;           // 0..7
    const int bcol = (tid & 31) * 4;     // 0..124

    const float* Aptr = A + (size_t)(row0 + arow) * 1024 + acol;
    const float* Bptr = W + (size_t)brow * 1024 + col0 + bcol;

    float acc[8][8];
    #pragma unroll
    for (int i = 0; i < 8; i++)
        #pragma unroll
        for (int j = 0; j < 8; j++) acc[i][j] = 0.f;

    for (int kt = 0; kt < 1024; kt += 8) {
        float4 av = *(const float4*)(Aptr + kt);
        float4 bv = *(const float4*)(Bptr + (size_t)kt * 1024);
        As[acol + 0][arow] = av.x;
        As[acol + 1][arow] = av.y;
        As[acol + 2][arow] = av.z;
        As[acol + 3][arow] = av.w;
        *(float4*)&Bsm[brow][bcol] = bv;
        __syncthreads();

        #pragma unroll
        for (int k = 0; k < 8; k++) {
            float a[8], b[8];
            *(float4*)(a)     = *(const float4*)&As[k][ty * 8];
            *(float4*)(a + 4) = *(const float4*)&As[k][ty * 8 + 4];
            *(float4*)(b)     = *(const float4*)&Bsm[k][tx * 8];
            *(float4*)(b + 4) = *(const float4*)&Bsm[k][tx * 8 + 4];
            #pragma unroll
            for (int i = 0; i < 8; i++)
                #pragma unroll
                for (int j = 0; j < 8; j++)
                    acc[i][j] += a[i] * b[j];
        }
        __syncthreads();
    }

    float bb[8];
    *(float4*)(bb)     = *(const float4*)&bias[col0 + tx * 8];
    *(float4*)(bb + 4) = *(const float4*)&bias[col0 + tx * 8 + 4];

    #pragma unroll
    for (int i = 0; i < 8; i++) {
        const int gr = row0 + ty * 8 + i;
        float4 o0, o1;
        o0.x = acc[i][0] + bb[0]; o0.y = acc[i][1] + bb[1];
        o0.z = acc[i][2] + bb[2]; o0.w = acc[i][3] + bb[3];
        o1.x = acc[i][4] + bb[4]; o1.y = acc[i][5] + bb[5];
        o1.z = acc[i][6] + bb[6]; o1.w = acc[i][7] + bb[7];
        *(float4*)&C[(size_t)gr * 1024 + col0 + tx * 8]     = o0;
        *(float4*)&C[(size_t)gr * 1024 + col0 + tx * 8 + 4] = o1;
    }
}

// ---------------------------------------------------------------------------
// Attention: one block per (bs, 16-query tile). Loops over all 16 heads.
// Dynamic smem layout (floats):
//   s_logits [16][1024]        16384
//   s_mask   [16][1024]        16384   (premultiplied by -1e9)
//   s_q      [16][64]           1024
//   s_kt     [64][257]         16448   (K chunk transposed; reused as V[128][64])
//   s_sum    [16]                 16   (stores 1/rowsum)
// total 50256 floats = 201024 bytes
// ---------------------------------------------------------------------------
#define ATTN_SMEM_FLOATS (16*1024 + 16*1024 + 16*64 + 64*257 + 16)
#define ATTN_SMEM_BYTES  (ATTN_SMEM_FLOATS * 4)

__global__ __launch_bounds__(256, 1) void attn_kernel(
    const float* __restrict__ Qp, const float* __restrict__ Kp,
    const float* __restrict__ Vp, const float* __restrict__ mask,
    float* __restrict__ Ctx, float* __restrict__ amean)
{
    extern __shared__ float sm[];
    float* s_logits = sm;                       // 16*1024
    float* s_mask   = s_logits + 16 * 1024;     // 16*1024
    float* s_q      = s_mask + 16 * 1024;       // 16*64
    float* s_kt     = s_q + 16 * 64;            // 64*257 (also V[128][64])
    float* s_sum    = s_kt + 64 * 257;          // 16

    const int tid = threadIdx.x;
    const int bs = blockIdx.y;
    const int q0 = blockIdx.x * QT;
    const size_t tok0 = (size_t)bs * LL + q0;

    // mask tile, premultiplied by NEG
    const float* mptr = mask + ((size_t)bs * LL + q0) * LL;
    #pragma unroll 4
    for (int i = 0; i < 64; i++) {
        int idx = tid + 256 * i;
        s_mask[idx] = mptr[idx] * -1.0e9f;
    }

    float mean_acc[64];
    #pragma unroll
    for (int i = 0; i < 64; i++) mean_acc[i] = 0.f;

    const int warp = tid >> 5, lane = tid & 31;
    const int kcol = tid & 63;        // QK: column base within chunk
    const int r_pv = tid >> 4;        // PV: row (0..15)
    const int dg   = (tid & 15) * 4;  // PV: depth group

    for (int h = 0; h < HH; h++) {
        __syncthreads();   // protect smem reuse across head iterations

        // ---- load Q tile (scaled by 1/sqrt(64)) ----
        #pragma unroll
        for (int i = 0; i < 4; i++) {
            int idx = tid + 256 * i;      // 0..1023
            int r = idx >> 6, d = idx & 63;
            s_q[r * 64 + d] = Qp[(tok0 + r) * 1024 + h * 64 + d] * 0.125f;
        }

        // ---- QK^T in chunks of 256 key columns ----
        for (int kb = 0; kb < LL; kb += 256) {
            __syncthreads();
            // stage K chunk transposed: s_kt[d][kr]
            #pragma unroll 4
            for (int i = 0; i < 64; i++) {
                int idx = tid + 256 * i;       // 0..16383
                int kr = idx >> 6, d = idx & 63;
                s_kt[d * 257 + kr] =
                    Kp[((size_t)bs * LL + kb + kr) * 1024 + h * 64 + d];
            }
            __syncthreads();

            // thread computes 16 rows x 4 cols (kcol, +64, +128, +192)
            float acc[16][4];
            #pragma unroll
            for (int r = 0; r < 16; r++) {
                acc[r][0] = 0.f; acc[r][1] = 0.f; acc[r][2] = 0.f; acc[r][3] = 0.f;
            }
            #pragma unroll 8
            for (int d = 0; d < 64; d++) {
                float kv0 = s_kt[d * 257 + kcol];
                float kv1 = s_kt[d * 257 + kcol + 64];
                float kv2 = s_kt[d * 257 + kcol + 128];
                float kv3 = s_kt[d * 257 + kcol + 192];
                #pragma unroll
                for (int r = 0; r < 16; r++) {
                    float qv = s_q[r * 64 + d];
                    acc[r][0] += qv * kv0;
                    acc[r][1] += qv * kv1;
                    acc[r][2] += qv * kv2;
                    acc[r][3] += qv * kv3;
                }
            }
            // write logits + mask
            #pragma unroll
            for (int r = 0; r < 16; r++) {
                #pragma unroll
                for (int j = 0; j < 4; j++) {
                    int k = kb + kcol + 64 * j;
                    s_logits[r * 1024 + k] = acc[r][j] + s_mask[r * 1024 + k];
                }
            }
        }
        __syncthreads();

        // ---- softmax: warp w handles rows w and w+8 ----
        #pragma unroll
        for (int rr = 0; rr < 2; rr++) {
            int r = warp + rr * 8;
            float m = -3.4e38f;
            #pragma unroll 8
            for (int j = 0; j < 32; j++)
                m = fmaxf(m, s_logits[r * 1024 + lane + 32 * j]);
            #pragma unroll
            for (int off = 16; off > 0; off >>= 1)
                m = fmaxf(m, __shfl_xor_sync(0xFFFFFFFFu, m, off));
            float ssum = 0.f;
            #pragma unroll 8
            for (int j = 0; j < 32; j++) {
                int idx = r * 1024 + lane + 32 * j;
                float p = __expf(s_logits[idx] - m);
                s_logits[idx] = p;
                ssum += p;
            }
            #pragma unroll
            for (int off = 16; off > 0; off >>= 1)
                ssum += __shfl_xor_sync(0xFFFFFFFFu, ssum, off);
            if (lane == 0) s_sum[r] = 1.f / ssum;
        }
        __syncthreads();

        // ---- accumulate attention mean (registers, thread-owned elements) ----
        #pragma unroll 8
        for (int i = 0; i < 64; i++) {
            int idx = tid + 256 * i;
            int r = idx >> 10;
            mean_acc[i] += s_logits[idx] * s_sum[r];
        }

        // ---- PV: chunks of 128 keys; V staged in s_kt region ----
        float* s_v = s_kt;
        float c0 = 0.f, c1 = 0.f, c2 = 0.f, c3 = 0.f;
        for (int kb = 0; kb < LL; kb += 128) {
            __syncthreads();
            #pragma unroll 4
            for (int i = 0; i < 32; i++) {
                int idx = tid + 256 * i;   // 0..8191
                int kr = idx >> 6, d = idx & 63;
                s_v[kr * 64 + d] =
                    Vp[((size_t)bs * LL + kb + kr) * 1024 + h * 64 + d];
            }
            __syncthreads();
            #pragma unroll 8
            for (int k = 0; k < 128; k++) {
                float p = s_logits[r_pv * 1024 + kb + k];
                float4 v = *(const float4*)&s_v[k * 64 + dg];
                c0 += p * v.x; c1 += p * v.y; c2 += p * v.z; c3 += p * v.w;
            }
        }
        {
            float inv = s_sum[r_pv];
            float4 o;
            o.x = c0 * inv; o.y = c1 * inv; o.z = c2 * inv; o.w = c3 * inv;
            *(float4*)&Ctx[(tok0 + r_pv) * 1024 + h * 64 + dg] = o;
        }
    }

    // ---- write attn mean (mean over 16 heads) ----
    float* aout = amean + ((size_t)bs * LL + q0) * LL;
    #pragma unroll 8
    for (int i = 0; i < 64; i++) {
        int idx = tid + 256 * i;
        aout[idx] = mean_acc[i] * (1.f / 16.f);
    }
}

// ---------------------------------------------------------------------------
extern "C" void kernel_launch(void* const* d_in, const int* in_sizes, int n_in,
                              void* d_out, int out_size)
{
    const float* q    = (const float*)d_in[0];
    const float* k    = (const float*)d_in[1];
    const float* v    = (const float*)d_in[2];
    const float* mask = (const float*)d_in[3];
    const float* wq   = (const float*)d_in[4];
    const float* bq   = (const float*)d_in[5];
    const float* wk   = (const float*)d_in[6];
    const float* bk   = (const float*)d_in[7];
    const float* wv   = (const float*)d_in[8];
    const float* bv   = (const float*)d_in[9];
    const float* wo   = (const float*)d_in[10];
    const float* bo   = (const float*)d_in[11];

    float* out   = (float*)d_out;                       // [B,S,L,D]
    float* amean = out + (size_t)NTOK * DD;             // [B,S,L,L]

    float *qp, *kp, *vp, *ctx;
    cudaGetSymbolAddress((void**)&qp,  g_qp);
    cudaGetSymbolAddress((void**)&kp,  g_kp);
    cudaGetSymbolAddress((void**)&vp,  g_vp);
    cudaGetSymbolAddress((void**)&ctx, g_ctx);

    static int smem_set = 0;
    if (!smem_set) {
        cudaFuncSetAttribute(attn_kernel,
                             cudaFuncAttributeMaxDynamicSharedMemorySize,
                             ATTN_SMEM_BYTES);
        smem_set = 1;
    }

    dim3 gemm_grid(8, 128);   // N/128, M/128
    sgemm_bias_kernel<<<gemm_grid, 256>>>(q, wq, bq, qp);
    sgemm_bias_kernel<<<gemm_grid, 256>>>(k, wk, bk, kp);
    sgemm_bias_kernel<<<gemm_grid, 256>>>(v, wv, bv, vp);

    dim3 attn_grid(LL / QT, BS);
    attn_kernel<<<attn_grid, 256, ATTN_SMEM_BYTES>>>(qp, kp, vp, mask, ctx, amean);

    sgemm_bias_kernel<<<gemm_grid, 256>>>(ctx, wo, bo, out);
}

// round 10
// speedup vs baseline: 1.1817x; 1.1817x over previous
#include <cuda_runtime.h>
#include <cuda_bf16.h>
#include <math.h>
#include <stdint.h>

// Problem constants
#define LL    1024      // seq len
#define DD    1024      // d_model
#define HH    16        // heads
#define DPT   64        // depth per head
#define BS    16        // B*S
#define NTOK  16384     // BS*LL
#define QT    16        // queries per attention block

// Scratch (static device globals; no runtime allocation)
__device__ float g_qp[NTOK * DD];
__device__ float g_kp[NTOK * DD];
__device__ float g_vp[NTOK * DD];
__device__ float g_ctx[NTOK * DD];
__device__ __nv_bfloat16 g_ah[NTOK * DD];   // activation hi
__device__ __nv_bfloat16 g_al[NTOK * DD];   // activation lo
__device__ __nv_bfloat16 g_wh[DD * DD];     // weight^T hi  [n][k]
__device__ __nv_bfloat16 g_wl[DD * DD];     // weight^T lo  [n][k]

// ===========================================================================
// helpers
// ===========================================================================
__device__ __forceinline__ uint32_t smem_to_u32(const void* smem_ptr) {
    uint32_t addr;
    asm("{ .reg .u64 tmp; cvta.to.shared.u64 tmp, %1; cvt.u32.u64 %0, tmp; }"
        : "=r"(addr) : "l"(smem_ptr));
    return addr;
}

#define CP_ASYNC16(dst_u32, src_ptr) \
    asm volatile("cp.async.cg.shared.global [%0], [%1], 16;" \
                 :: "r"(dst_u32), "l"(src_ptr) : "memory")
#define CP_COMMIT() \
    asm volatile("cp.async.commit_group;" ::: "memory")
#define CP_WAIT(N) \
    asm volatile("cp.async.wait_group %0;" :: "n"(N) : "memory")

#define LDSM4(r, addr) \
    asm volatile("ldmatrix.sync.aligned.m8n8.x4.shared.b16 {%0,%1,%2,%3}, [%4];" \
                 : "=r"((r)[0]), "=r"((r)[1]), "=r"((r)[2]), "=r"((r)[3]) \
                 : "r"(addr))
#define LDSM2(r, addr) \
    asm volatile("ldmatrix.sync.aligned.m8n8.x2.shared.b16 {%0,%1}, [%2];" \
                 : "=r"((r)[0]), "=r"((r)[1]) : "r"(addr))

#define MMA16816(d, a, b) \
    asm volatile("mma.sync.aligned.m16n8k16.row.col.f32.bf16.bf16.f32 " \
                 "{%0,%1,%2,%3}, {%4,%5,%6,%7}, {%8,%9}, {%0,%1,%2,%3};" \
                 : "+f"((d)[0]), "+f"((d)[1]), "+f"((d)[2]), "+f"((d)[3]) \
                 : "r"((a)[0]), "r"((a)[1]), "r"((a)[2]), "r"((a)[3]), \
                   "r"((b)[0]), "r"((b)[1]))

// ===========================================================================
// Conversion kernels: fp32 -> bf16 hi/lo split
// ===========================================================================
__global__ __launch_bounds__(256) void conv_split(
    const float* __restrict__ A,
    __nv_bfloat16* __restrict__ H, __nv_bfloat16* __restrict__ L)
{
    size_t i = ((size_t)blockIdx.x * 256 + threadIdx.x) * 4;
    float4 v = *(const float4*)(A + i);
    __nv_bfloat16 h0 = __float2bfloat16(v.x);
    __nv_bfloat16 h1 = __float2bfloat16(v.y);
    __nv_bfloat16 h2 = __float2bfloat16(v.z);
    __nv_bfloat16 h3 = __float2bfloat16(v.w);
    __nv_bfloat16 l0 = __float2bfloat16(v.x - __bfloat162float(h0));
    __nv_bfloat16 l1 = __float2bfloat16(v.y - __bfloat162float(h1));
    __nv_bfloat16 l2 = __float2bfloat16(v.z - __bfloat162float(h2));
    __nv_bfloat16 l3 = __float2bfloat16(v.w - __bfloat162float(h3));
    __nv_bfloat162 hh0; hh0.x = h0; hh0.y = h1;
    __nv_bfloat162 hh1; hh1.x = h2; hh1.y = h3;
    __nv_bfloat162 ll0; ll0.x = l0; ll0.y = l1;
    __nv_bfloat162 ll1; ll1.x = l2; ll1.y = l3;
    *(__nv_bfloat162*)(H + i)     = hh0;
    *(__nv_bfloat162*)(H + i + 2) = hh1;
    *(__nv_bfloat162*)(L + i)     = ll0;
    *(__nv_bfloat162*)(L + i + 2) = ll1;
}

// Transpose + split: W[k][n] (1024x1024) -> Wt_hi[n][k], Wt_lo[n][k]
__global__ __launch_bounds__(256) void conv_wt(
    const float* __restrict__ W,
    __nv_bfloat16* __restrict__ Th, __nv_bfloat16* __restrict__ Tl)
{
    __shared__ float t[32][33];
    const int n0 = blockIdx.x * 32, k0 = blockIdx.y * 32;
    const int tx = threadIdx.x & 31, ty = threadIdx.x >> 5;   // 32 x 8
    #pragma unroll
    for (int j = 0; j < 32; j += 8)
        t[ty + j][tx] = W[(size_t)(k0 + ty + j) * 1024 + n0 + tx];
    __syncthreads();
    #pragma unroll
    for (int j = 0; j < 32; j += 8) {
        float v = t[tx][ty + j];
        __nv_bfloat16 h = __float2bfloat16(v);
        __nv_bfloat16 l = __float2bfloat16(v - __bfloat162float(h));
        size_t o = (size_t)(n0 + ty + j) * 1024 + k0 + tx;
        Th[o] = h;
        Tl[o] = l;
    }
}

// ===========================================================================
// mma.sync GEMM: C[16384,1024] = A @ W + bias, bf16x3 error-compensated.
// A as (Ah, Al) row-major [m][k]; W as (Bh, Bl) = W^T [n][k].
// CTA tile 128x128, 8 warps (2x4), warp tile 64x32, BK=64,
// cp.async double-buffered smem, fp32 register accumulators.
// ===========================================================================
#define STR    72                     // padded k-stride (elems) -> 144 bytes
#define TILE_B (128 * STR * 2)        // 18432 bytes per operand tile
#define STAGE_B (4 * TILE_B)          // 73728 bytes per stage
#define GEMM_SMEM_BYTES (2 * STAGE_B) // 147456

__global__ __launch_bounds__(256, 1) void gemm_mma(
    const __nv_bfloat16* __restrict__ Ah, const __nv_bfloat16* __restrict__ Al,
    const __nv_bfloat16* __restrict__ Bh, const __nv_bfloat16* __restrict__ Bl,
    const float* __restrict__ bias, float* __restrict__ C)
{
    extern __shared__ char smc[];
    const uint32_t smb = smem_to_u32(smc);
    const int tid = threadIdx.x;
    const int lane = tid & 31, wid = tid >> 5;
    const int wm = wid & 1;        // 0..1  (m half, 64 rows each)
    const int wn = wid >> 1;       // 0..3  (n quarter, 32 cols each)
    const int m0 = blockIdx.y * 128, n0 = blockIdx.x * 128;

    const __nv_bfloat16* srcs[4] = {
        Ah + (size_t)m0 * 1024, Al + (size_t)m0 * 1024,
        Bh + (size_t)n0 * 1024, Bl + (size_t)n0 * 1024 };

    const int rb = tid >> 3;       // load row base (0..31)
    const int g  = tid & 7;        // 16B granule within 128B row chunk

    float acc[4][4][4];
    #pragma unroll
    for (int mt = 0; mt < 4; mt++)
        #pragma unroll
        for (int nt = 0; nt < 4; nt++)
            #pragma unroll
            for (int e = 0; e < 4; e++) acc[mt][nt][e] = 0.f;

    // ---- stage loader (cp.async) ----
    auto load_stage = [&](int c, int buf) {
        const int kc = c * 64;
        #pragma unroll
        for (int t = 0; t < 4; t++) {
            const __nv_bfloat16* sp = srcs[t];
            const uint32_t db = smb + buf * STAGE_B + t * TILE_B;
            #pragma unroll
            for (int it = 0; it < 4; it++) {
                const int row = rb + 32 * it;
                const uint32_t dst = db + (uint32_t)row * 144 + g * 16;
                const __nv_bfloat16* src = sp + (size_t)row * 1024 + kc + g * 8;
                CP_ASYNC16(dst, src);
            }
        }
    };

    load_stage(0, 0);
    CP_COMMIT();

    for (int c = 0; c < 16; c++) {
        const int buf = c & 1;
        if (c < 15) {
            load_stage(c + 1, buf ^ 1);
            CP_COMMIT();
            CP_WAIT(1);
        } else {
            CP_WAIT(0);
        }
        __syncthreads();

        const uint32_t bA = smb + buf * STAGE_B;
        #pragma unroll
        for (int ks = 0; ks < 4; ks++) {
            uint32_t a_h[4][4], a_l[4][4], b_h[4][2], b_l[4][2];
            const uint32_t acol = (uint32_t)(ks * 16 + (lane >> 4) * 8) * 2;
            #pragma unroll
            for (int mt = 0; mt < 4; mt++) {
                const uint32_t off =
                    (uint32_t)((wm * 64 + mt * 16 + (lane & 15)) * STR) * 2 + acol;
                LDSM4(a_h[mt], bA + off);
                LDSM4(a_l[mt], bA + TILE_B + off);
            }
            const uint32_t bcol = (uint32_t)(ks * 16 + ((lane >> 3) & 1) * 8) * 2;
            #pragma unroll
            for (int nt = 0; nt < 4; nt++) {
                const uint32_t off =
                    (uint32_t)((wn * 32 + nt * 8 + (lane & 7)) * STR) * 2 + bcol;
                LDSM2(b_h[nt], bA + 2 * TILE_B + off);
                LDSM2(b_l[nt], bA + 3 * TILE_B + off);
            }
            #pragma unroll
            for (int mt = 0; mt < 4; mt++)
                #pragma unroll
                for (int nt = 0; nt < 4; nt++) {
                    MMA16816(acc[mt][nt], a_h[mt], b_h[nt]);
                    MMA16816(acc[mt][nt], a_h[mt], b_l[nt]);
                    MMA16816(acc[mt][nt], a_l[mt], b_h[nt]);
                }
        }
        __syncthreads();
    }

    // ---- epilogue: fragment layout d[m = lane/4 (+8)][n = 2*(lane%4)+e] ----
    #pragma unroll
    for (int mt = 0; mt < 4; mt++) {
        const int row_lo = m0 + wm * 64 + mt * 16 + (lane >> 2);
        #pragma unroll
        for (int nt = 0; nt < 4; nt++) {
            const int col = n0 + wn * 32 + nt * 8 + (lane & 3) * 2;
            const float2 bb = __ldg((const float2*)(bias + col));
            float2 o0, o1;
            o0.x = acc[mt][nt][0] + bb.x;
            o0.y = acc[mt][nt][1] + bb.y;
            o1.x = acc[mt][nt][2] + bb.x;
            o1.y = acc[mt][nt][3] + bb.y;
            *(float2*)&C[(size_t)row_lo * 1024 + col]       = o0;
            *(float2*)&C[(size_t)(row_lo + 8) * 1024 + col] = o1;
        }
    }
}

// ---------------------------------------------------------------------------
// Attention: one block per (bs, 16-query tile). Loops over all 16 heads.
// (unchanged from the passing R4 kernel)
// ---------------------------------------------------------------------------
#define ATTN_SMEM_FLOATS (16*1024 + 16*1024 + 16*64 + 64*257 + 16)
#define ATTN_SMEM_BYTES  (ATTN_SMEM_FLOATS * 4)

__global__ __launch_bounds__(256, 1) void attn_kernel(
    const float* __restrict__ Qp, const float* __restrict__ Kp,
    const float* __restrict__ Vp, const float* __restrict__ mask,
    float* __restrict__ Ctx, float* __restrict__ amean)
{
    extern __shared__ float smf[];
    float* s_logits = smf;                      // 16*1024
    float* s_mask   = s_logits + 16 * 1024;     // 16*1024
    float* s_q      = s_mask + 16 * 1024;       // 16*64
    float* s_kt     = s_q + 16 * 64;            // 64*257 (also V[128][64])
    float* s_sum    = s_kt + 64 * 257;          // 16

    const int tid = threadIdx.x;
    const int bs = blockIdx.y;
    const int q0 = blockIdx.x * QT;
    const size_t tok0 = (size_t)bs * LL + q0;

    const float* mptr = mask + ((size_t)bs * LL + q0) * LL;
    #pragma unroll 4
    for (int i = 0; i < 64; i++) {
        int idx = tid + 256 * i;
        s_mask[idx] = mptr[idx] * -1.0e9f;
    }

    float mean_acc[64];
    #pragma unroll
    for (int i = 0; i < 64; i++) mean_acc[i] = 0.f;

    const int warp = tid >> 5, lane = tid & 31;
    const int kcol = tid & 63;
    const int r_pv = tid >> 4;
    const int dg   = (tid & 15) * 4;

    for (int h = 0; h < HH; h++) {
        __syncthreads();

        #pragma unroll
        for (int i = 0; i < 4; i++) {
            int idx = tid + 256 * i;
            int r = idx >> 6, d = idx & 63;
            s_q[r * 64 + d] = Qp[(tok0 + r) * 1024 + h * 64 + d] * 0.125f;
        }

        for (int kb = 0; kb < LL; kb += 256) {
            __syncthreads();
            #pragma unroll 4
            for (int i = 0; i < 64; i++) {
                int idx = tid + 256 * i;
                int kr = idx >> 6, d = idx & 63;
                s_kt[d * 257 + kr] =
                    Kp[((size_t)bs * LL + kb + kr) * 1024 + h * 64 + d];
            }
            __syncthreads();

            float acc[16][4];
            #pragma unroll
            for (int r = 0; r < 16; r++) {
                acc[r][0] = 0.f; acc[r][1] = 0.f; acc[r][2] = 0.f; acc[r][3] = 0.f;
            }
            #pragma unroll 8
            for (int d = 0; d < 64; d++) {
                float kv0 = s_kt[d * 257 + kcol];
                float kv1 = s_kt[d * 257 + kcol + 64];
                float kv2 = s_kt[d * 257 + kcol + 128];
                float kv3 = s_kt[d * 257 + kcol + 192];
                #pragma unroll
                for (int r = 0; r < 16; r++) {
                    float qv = s_q[r * 64 + d];
                    acc[r][0] += qv * kv0;
                    acc[r][1] += qv * kv1;
                    acc[r][2] += qv * kv2;
                    acc[r][3] += qv * kv3;
                }
            }
            #pragma unroll
            for (int r = 0; r < 16; r++) {
                #pragma unroll
                for (int j = 0; j < 4; j++) {
                    int k = kb + kcol + 64 * j;
                    s_logits[r * 1024 + k] = acc[r][j] + s_mask[r * 1024 + k];
                }
            }
        }
        __syncthreads();

        #pragma unroll
        for (int rr = 0; rr < 2; rr++) {
            int r = warp + rr * 8;
            float m = -3.4e38f;
            #pragma unroll 8
            for (int j = 0; j < 32; j++)
                m = fmaxf(m, s_logits[r * 1024 + lane + 32 * j]);
            #pragma unroll
            for (int off = 16; off > 0; off >>= 1)
                m = fmaxf(m, __shfl_xor_sync(0xFFFFFFFFu, m, off));
            float ssum = 0.f;
            #pragma unroll 8
            for (int j = 0; j < 32; j++) {
                int idx = r * 1024 + lane + 32 * j;
                float p = __expf(s_logits[idx] - m);
                s_logits[idx] = p;
                ssum += p;
            }
            #pragma unroll
            for (int off = 16; off > 0; off >>= 1)
                ssum += __shfl_xor_sync(0xFFFFFFFFu, ssum, off);
            if (lane == 0) s_sum[r] = 1.f / ssum;
        }
        __syncthreads();

        #pragma unroll 8
        for (int i = 0; i < 64; i++) {
            int idx = tid + 256 * i;
            int r = idx >> 10;
            mean_acc[i] += s_logits[idx] * s_sum[r];
        }

        float* s_v = s_kt;
        float c0 = 0.f, c1 = 0.f, c2 = 0.f, c3 = 0.f;
        for (int kb = 0; kb < LL; kb += 128) {
            __syncthreads();
            #pragma unroll 4
            for (int i = 0; i < 32; i++) {
                int idx = tid + 256 * i;
                int kr = idx >> 6, d = idx & 63;
                s_v[kr * 64 + d] =
                    Vp[((size_t)bs * LL + kb + kr) * 1024 + h * 64 + d];
            }
            __syncthreads();
            #pragma unroll 8
            for (int k = 0; k < 128; k++) {
                float p = s_logits[r_pv * 1024 + kb + k];
                float4 v = *(const float4*)&s_v[k * 64 + dg];
                c0 += p * v.x; c1 += p * v.y; c2 += p * v.z; c3 += p * v.w;
            }
        }
        {
            float inv = s_sum[r_pv];
            float4 o;
            o.x = c0 * inv; o.y = c1 * inv; o.z = c2 * inv; o.w = c3 * inv;
            *(float4*)&Ctx[(tok0 + r_pv) * 1024 + h * 64 + dg] = o;
        }
    }

    float* aout = amean + ((size_t)bs * LL + q0) * LL;
    #pragma unroll 8
    for (int i = 0; i < 64; i++) {
        int idx = tid + 256 * i;
        aout[idx] = mean_acc[i] * (1.f / 16.f);
    }
}

// ---------------------------------------------------------------------------
extern "C" void kernel_launch(void* const* d_in, const int* in_sizes, int n_in,
                              void* d_out, int out_size)
{
    const float* q    = (const float*)d_in[0];
    const float* k    = (const float*)d_in[1];
    const float* v    = (const float*)d_in[2];
    const float* mask = (const float*)d_in[3];
    const float* wq   = (const float*)d_in[4];
    const float* bq   = (const float*)d_in[5];
    const float* wk   = (const float*)d_in[6];
    const float* bk   = (const float*)d_in[7];
    const float* wv   = (const float*)d_in[8];
    const float* bv   = (const float*)d_in[9];
    const float* wo   = (const float*)d_in[10];
    const float* bo   = (const float*)d_in[11];

    float* out   = (float*)d_out;                       // [B,S,L,D]
    float* amean = out + (size_t)NTOK * DD;             // [B,S,L,L]

    float *qp, *kp, *vp, *ctx;
    __nv_bfloat16 *ah, *al, *wh, *wl;
    cudaGetSymbolAddress((void**)&qp,  g_qp);
    cudaGetSymbolAddress((void**)&kp,  g_kp);
    cudaGetSymbolAddress((void**)&vp,  g_vp);
    cudaGetSymbolAddress((void**)&ctx, g_ctx);
    cudaGetSymbolAddress((void**)&ah,  g_ah);
    cudaGetSymbolAddress((void**)&al,  g_al);
    cudaGetSymbolAddress((void**)&wh,  g_wh);
    cudaGetSymbolAddress((void**)&wl,  g_wl);

    static int attr_set = 0;
    if (!attr_set) {
        cudaFuncSetAttribute(attn_kernel,
                             cudaFuncAttributeMaxDynamicSharedMemorySize,
                             ATTN_SMEM_BYTES);
        cudaFuncSetAttribute(gemm_mma,
                             cudaFuncAttributeMaxDynamicSharedMemorySize,
                             GEMM_SMEM_BYTES);
        attr_set = 1;
    }

    const dim3 gemm_grid(8, 128);        // N/128, M/128
    const dim3 wt_grid(32, 32);
    const int  conv_blocks = (NTOK * DD) / (256 * 4);   // 16384

    // Q projection
    conv_wt<<<wt_grid, 256>>>(wq, wh, wl);
    conv_split<<<conv_blocks, 256>>>(q, ah, al);
    gemm_mma<<<gemm_grid, 256, GEMM_SMEM_BYTES>>>(ah, al, wh, wl, bq, qp);
    // K projection
    conv_wt<<<wt_grid, 256>>>(wk, wh, wl);
    conv_split<<<conv_blocks, 256>>>(k, ah, al);
    gemm_mma<<<gemm_grid, 256, GEMM_SMEM_BYTES>>>(ah, al, wh, wl, bk, kp);
    // V projection
    conv_wt<<<wt_grid, 256>>>(wv, wh, wl);
    conv_split<<<conv_blocks, 256>>>(v, ah, al);
    gemm_mma<<<gemm_grid, 256, GEMM_SMEM_BYTES>>>(ah, al, wh, wl, bv, vp);

    // Attention (fp32, unchanged)
    dim3 attn_grid(LL / QT, BS);
    attn_kernel<<<attn_grid, 256, ATTN_SMEM_BYTES>>>(qp, kp, vp, mask, ctx, amean);

    // Output projection
    conv_wt<<<wt_grid, 256>>>(wo, wh, wl);
    conv_split<<<conv_blocks, 256>>>(ctx, ah, al);
    gemm_mma<<<gemm_grid, 256, GEMM_SMEM_BYTES>>>(ah, al, wh, wl, bo, out);
}

// round 11
// speedup vs baseline: 4.8446x; 4.0996x over previous
#include <cuda_runtime.h>
#include <cuda_bf16.h>
#include <math.h>
#include <stdint.h>

// Problem constants
#define LL    1024
#define DD    1024
#define HH    16
#define DPT   64
#define BS    16
#define NTOK  16384

// Scratch (static device globals; no runtime allocation)
__device__ float g_ctx[NTOK * DD];
__device__ __nv_bfloat16 g_ah[NTOK * DD];
__device__ __nv_bfloat16 g_al[NTOK * DD];
__device__ __nv_bfloat16 g_wh[DD * DD];
__device__ __nv_bfloat16 g_wl[DD * DD];
__device__ __nv_bfloat16 g_qh[NTOK * DD];
__device__ __nv_bfloat16 g_ql[NTOK * DD];
__device__ __nv_bfloat16 g_kh[NTOK * DD];
__device__ __nv_bfloat16 g_kl[NTOK * DD];
__device__ __nv_bfloat16 g_vh[NTOK * DD];
__device__ __nv_bfloat16 g_vl[NTOK * DD];

// ===========================================================================
// helpers
// ===========================================================================
__device__ __forceinline__ uint32_t smem_to_u32(const void* smem_ptr) {
    uint32_t addr;
    asm("{ .reg .u64 tmp; cvta.to.shared.u64 tmp, %1; cvt.u32.u64 %0, tmp; }"
        : "=r"(addr) : "l"(smem_ptr));
    return addr;
}

#define CP_ASYNC16(dst_u32, src_ptr) \
    asm volatile("cp.async.cg.shared.global [%0], [%1], 16;" \
                 :: "r"(dst_u32), "l"(src_ptr) : "memory")
#define CP_COMMIT() \
    asm volatile("cp.async.commit_group;" ::: "memory")
#define CP_WAIT(N) \
    asm volatile("cp.async.wait_group %0;" :: "n"(N) : "memory")

#define LDSM4(r, addr) \
    asm volatile("ldmatrix.sync.aligned.m8n8.x4.shared.b16 {%0,%1,%2,%3}, [%4];" \
                 : "=r"((r)[0]), "=r"((r)[1]), "=r"((r)[2]), "=r"((r)[3]) \
                 : "r"(addr))
#define LDSM2(r, addr) \
    asm volatile("ldmatrix.sync.aligned.m8n8.x2.shared.b16 {%0,%1}, [%2];" \
                 : "=r"((r)[0]), "=r"((r)[1]) : "r"(addr))
#define LDSM2T(r, addr) \
    asm volatile("ldmatrix.sync.aligned.m8n8.x2.trans.shared.b16 {%0,%1}, [%2];" \
                 : "=r"((r)[0]), "=r"((r)[1]) : "r"(addr))

#define MMA16816(d, a, b) \
    asm volatile("mma.sync.aligned.m16n8k16.row.col.f32.bf16.bf16.f32 " \
                 "{%0,%1,%2,%3}, {%4,%5,%6,%7}, {%8,%9}, {%0,%1,%2,%3};" \
                 : "+f"((d)[0]), "+f"((d)[1]), "+f"((d)[2]), "+f"((d)[3]) \
                 : "r"((a)[0]), "r"((a)[1]), "r"((a)[2]), "r"((a)[3]), \
                   "r"((b)[0]), "r"((b)[1]))

// ===========================================================================
// Conversion kernels: fp32 -> bf16 hi/lo split
// ===========================================================================
__global__ __launch_bounds__(256) void conv_split(
    const float* __restrict__ A,
    __nv_bfloat16* __restrict__ H, __nv_bfloat16* __restrict__ L)
{
    size_t i = ((size_t)blockIdx.x * 256 + threadIdx.x) * 4;
    float4 v = *(const float4*)(A + i);
    __nv_bfloat16 h0 = __float2bfloat16(v.x);
    __nv_bfloat16 h1 = __float2bfloat16(v.y);
    __nv_bfloat16 h2 = __float2bfloat16(v.z);
    __nv_bfloat16 h3 = __float2bfloat16(v.w);
    __nv_bfloat16 l0 = __float2bfloat16(v.x - __bfloat162float(h0));
    __nv_bfloat16 l1 = __float2bfloat16(v.y - __bfloat162float(h1));
    __nv_bfloat16 l2 = __float2bfloat16(v.z - __bfloat162float(h2));
    __nv_bfloat16 l3 = __float2bfloat16(v.w - __bfloat162float(h3));
    __nv_bfloat162 hh0; hh0.x = h0; hh0.y = h1;
    __nv_bfloat162 hh1; hh1.x = h2; hh1.y = h3;
    __nv_bfloat162 ll0; ll0.x = l0; ll0.y = l1;
    __nv_bfloat162 ll1; ll1.x = l2; ll1.y = l3;
    *(__nv_bfloat162*)(H + i)     = hh0;
    *(__nv_bfloat162*)(H + i + 2) = hh1;
    *(__nv_bfloat162*)(L + i)     = ll0;
    *(__nv_bfloat162*)(L + i + 2) = ll1;
}

__global__ __launch_bounds__(256) void conv_wt(
    const float* __restrict__ W,
    __nv_bfloat16* __restrict__ Th, __nv_bfloat16* __restrict__ Tl)
{
    __shared__ float t[32][33];
    const int n0 = blockIdx.x * 32, k0 = blockIdx.y * 32;
    const int tx = threadIdx.x & 31, ty = threadIdx.x >> 5;
    #pragma unroll
    for (int j = 0; j < 32; j += 8)
        t[ty + j][tx] = W[(size_t)(k0 + ty + j) * 1024 + n0 + tx];
    __syncthreads();
    #pragma unroll
    for (int j = 0; j < 32; j += 8) {
        float v = t[tx][ty + j];
        __nv_bfloat16 h = __float2bfloat16(v);
        __nv_bfloat16 l = __float2bfloat16(v - __bfloat162float(h));
        size_t o = (size_t)(n0 + ty + j) * 1024 + k0 + tx;
        Th[o] = h;
        Tl[o] = l;
    }
}

// ===========================================================================
// mma.sync GEMM (bf16x3). mode 0: C = fp32 + bias. mode 1: write bf16 hi/lo
// of (C+bias)*scale into OH/OL (for Q/K/V projections).
// ===========================================================================
#define STR    72
#define TILE_B (128 * STR * 2)
#define STAGE_B (4 * TILE_B)
#define GEMM_SMEM_BYTES (2 * STAGE_B)

__global__ __launch_bounds__(256, 1) void gemm_mma(
    const __nv_bfloat16* __restrict__ Ah, const __nv_bfloat16* __restrict__ Al,
    const __nv_bfloat16* __restrict__ Bh, const __nv_bfloat16* __restrict__ Bl,
    const float* __restrict__ bias, float* __restrict__ C,
    __nv_bfloat16* __restrict__ OH, __nv_bfloat16* __restrict__ OL,
    int mode, float scale)
{
    extern __shared__ char smc[];
    const uint32_t smb = smem_to_u32(smc);
    const int tid = threadIdx.x;
    const int lane = tid & 31, wid = tid >> 5;
    const int wm = wid & 1;
    const int wn = wid >> 1;
    const int m0 = blockIdx.y * 128, n0 = blockIdx.x * 128;

    const __nv_bfloat16* srcs[4] = {
        Ah + (size_t)m0 * 1024, Al + (size_t)m0 * 1024,
        Bh + (size_t)n0 * 1024, Bl + (size_t)n0 * 1024 };

    const int rb = tid >> 3;
    const int g  = tid & 7;

    float acc[4][4][4];
    #pragma unroll
    for (int mt = 0; mt < 4; mt++)
        #pragma unroll
        for (int nt = 0; nt < 4; nt++)
            #pragma unroll
            for (int e = 0; e < 4; e++) acc[mt][nt][e] = 0.f;

    auto load_stage = [&](int c, int buf) {
        const int kc = c * 64;
        #pragma unroll
        for (int t = 0; t < 4; t++) {
            const __nv_bfloat16* sp = srcs[t];
            const uint32_t db = smb + buf * STAGE_B + t * TILE_B;
            #pragma unroll
            for (int it = 0; it < 4; it++) {
                const int row = rb + 32 * it;
                const uint32_t dst = db + (uint32_t)row * 144 + g * 16;
                const __nv_bfloat16* src = sp + (size_t)row * 1024 + kc + g * 8;
                CP_ASYNC16(dst, src);
            }
        }
    };

    load_stage(0, 0);
    CP_COMMIT();

    for (int c = 0; c < 16; c++) {
        const int buf = c & 1;
        if (c < 15) {
            load_stage(c + 1, buf ^ 1);
            CP_COMMIT();
            CP_WAIT(1);
        } else {
            CP_WAIT(0);
        }
        __syncthreads();

        const uint32_t bA = smb + buf * STAGE_B;
        #pragma unroll
        for (int ks = 0; ks < 4; ks++) {
            uint32_t a_h[4][4], a_l[4][4], b_h[4][2], b_l[4][2];
            const uint32_t acol = (uint32_t)(ks * 16 + (lane >> 4) * 8) * 2;
            #pragma unroll
            for (int mt = 0; mt < 4; mt++) {
                const uint32_t off =
                    (uint32_t)((wm * 64 + mt * 16 + (lane & 15)) * STR) * 2 + acol;
                LDSM4(a_h[mt], bA + off);
                LDSM4(a_l[mt], bA + TILE_B + off);
            }
            const uint32_t bcol = (uint32_t)(ks * 16 + ((lane >> 3) & 1) * 8) * 2;
            #pragma unroll
            for (int nt = 0; nt < 4; nt++) {
                const uint32_t off =
                    (uint32_t)((wn * 32 + nt * 8 + (lane & 7)) * STR) * 2 + bcol;
                LDSM2(b_h[nt], bA + 2 * TILE_B + off);
                LDSM2(b_l[nt], bA + 3 * TILE_B + off);
            }
            #pragma unroll
            for (int mt = 0; mt < 4; mt++)
                #pragma unroll
                for (int nt = 0; nt < 4; nt++) {
                    MMA16816(acc[mt][nt], a_h[mt], b_h[nt]);
                    MMA16816(acc[mt][nt], a_h[mt], b_l[nt]);
                    MMA16816(acc[mt][nt], a_l[mt], b_h[nt]);
                }
        }
        __syncthreads();
    }

    #pragma unroll
    for (int mt = 0; mt < 4; mt++) {
        const int row_lo = m0 + wm * 64 + mt * 16 + (lane >> 2);
        #pragma unroll
        for (int nt = 0; nt < 4; nt++) {
            const int col = n0 + wn * 32 + nt * 8 + (lane & 3) * 2;
            const float2 bb = __ldg((const float2*)(bias + col));
            float v0 = acc[mt][nt][0] + bb.x;
            float v1 = acc[mt][nt][1] + bb.y;
            float v2 = acc[mt][nt][2] + bb.x;
            float v3 = acc[mt][nt][3] + bb.y;
            if (mode == 0) {
                float2 o0; o0.x = v0; o0.y = v1;
                float2 o1; o1.x = v2; o1.y = v3;
                *(float2*)&C[(size_t)row_lo * 1024 + col]       = o0;
                *(float2*)&C[(size_t)(row_lo + 8) * 1024 + col] = o1;
            } else {
                v0 *= scale; v1 *= scale; v2 *= scale; v3 *= scale;
                __nv_bfloat16 h0 = __float2bfloat16(v0);
                __nv_bfloat16 h1 = __float2bfloat16(v1);
                __nv_bfloat16 h2 = __float2bfloat16(v2);
                __nv_bfloat16 h3 = __float2bfloat16(v3);
                __nv_bfloat162 hp0; hp0.x = h0; hp0.y = h1;
                __nv_bfloat162 hp1; hp1.x = h2; hp1.y = h3;
                __nv_bfloat162 lp0;
                lp0.x = __float2bfloat16(v0 - __bfloat162float(h0));
                lp0.y = __float2bfloat16(v1 - __bfloat162float(h1));
                __nv_bfloat162 lp1;
                lp1.x = __float2bfloat16(v2 - __bfloat162float(h2));
                lp1.y = __float2bfloat16(v3 - __bfloat162float(h3));
                *(__nv_bfloat162*)&OH[(size_t)row_lo * 1024 + col]       = hp0;
                *(__nv_bfloat162*)&OH[(size_t)(row_lo + 8) * 1024 + col] = hp1;
                *(__nv_bfloat162*)&OL[(size_t)row_lo * 1024 + col]       = lp0;
                *(__nv_bfloat162*)&OL[(size_t)(row_lo + 8) * 1024 + col] = lp1;
            }
        }
    }
}

// ===========================================================================
// Tensor-core attention.
// Block = (q-tile of 32, bs). 512 threads = 16 warps. Loop 16 heads.
// smem layout (bytes):
//   OFF_LOG 0       : logits/p  32 x 1032 fp32|packed  = 132096
//   OFF_KV  132096  : K/V staging 2 stages x (hi+lo) 128x72 bf16 = 73728
//   OFF_Q   205824  : Q staging hi+lo 32x72 bf16 = 9216
//   OFF_MB  215040  : mask bits 32x1024/8 = 4096
//   OFF_INV 219136  : 32 fp32 inverse row sums = 128
//   total 219264
// ===========================================================================
#define LSTR 1032
#define KSTR2 144          // staging row stride bytes
#define OFF_KV  132096
#define OFF_Q   205824
#define OFF_MB  215040
#define OFF_INV 219136
#define AT_SMEM 219264
#define KVBUF   36864      // per stage (hi+lo)
#define KVPART  18432      // per hi or lo tile

__global__ __launch_bounds__(512, 1) void attn_tc(
    const __nv_bfloat16* __restrict__ Qh, const __nv_bfloat16* __restrict__ Ql,
    const __nv_bfloat16* __restrict__ Kh, const __nv_bfloat16* __restrict__ Kl,
    const __nv_bfloat16* __restrict__ Vh, const __nv_bfloat16* __restrict__ Vl,
    const float* __restrict__ mask,
    float* __restrict__ Ctx, float* __restrict__ amean)
{
    extern __shared__ char smc[];
    const uint32_t smb = smem_to_u32(smc);
    float*    s_log = (float*)smc;
    uint32_t* s_p   = (uint32_t*)smc;
    uint32_t* s_mb  = (uint32_t*)(smc + OFF_MB);
    float*    s_inv = (float*)(smc + OFF_INV);

    const int tid = threadIdx.x;
    const int lane = tid & 31, wid = tid >> 5;
    const int wm = wid & 1;        // m half (16 rows)
    const int wg = wid >> 1;       // 0..7: key-group (QK) / d-group (PV)
    const int bs = blockIdx.y;
    const int q0 = blockIdx.x * 32;
    const size_t tokbase = (size_t)bs * LL;

    // ---- pack mask bits ----
    {
        const float* mp = mask + (tokbase + q0) * LL;
        #pragma unroll 8
        for (int i = 0; i < 64; i++) {
            int linear = i * 512 + tid;
            float mv = mp[linear];
            unsigned b = __ballot_sync(0xFFFFFFFFu, mv != 0.0f);
            if (lane == 0) s_mb[linear >> 5] = b;
        }
    }

    float mean_acc[64];
    #pragma unroll
    for (int i = 0; i < 64; i++) mean_acc[i] = 0.f;

    // staging loaders
    auto load_kv = [&](const __nv_bfloat16* Hsrc, const __nv_bfloat16* Lsrc,
                       int kb, int buf, int h) {
        #pragma unroll
        for (int i = 0; i < 4; i++) {
            int gidx = tid + 512 * i;                 // 0..2047
            int part = gidx >> 10;                    // 0 hi, 1 lo
            int gg = gidx & 1023;
            int row = gg >> 3, d8 = gg & 7;
            const __nv_bfloat16* src = (part ? Lsrc : Hsrc) +
                (tokbase + kb * 128 + row) * 1024 + h * 64 + d8 * 8;
            uint32_t dst = smb + OFF_KV + buf * KVBUF + part * KVPART
                         + row * KSTR2 + d8 * 16;
            CP_ASYNC16(dst, src);
        }
    };

    __syncthreads();

    for (int h = 0; h < HH; h++) {
        // ---- Q staging (hi/lo), one 16B granule per thread ----
        {
            int part = tid >> 8;           // 0 hi, 1 lo
            int gg = tid & 255;
            int row = gg >> 3, d8 = gg & 7;
            const __nv_bfloat16* src = (part ? Ql : Qh) +
                (tokbase + q0 + row) * 1024 + h * 64 + d8 * 8;
            uint4 val = *(const uint4*)src;
            *(uint4*)(smc + OFF_Q + part * 4608 + row * KSTR2 + d8 * 16) = val;
        }
        load_kv(Kh, Kl, 0, 0, h);
        CP_COMMIT();

        // ---- QK^T over 8 chunks of 128 keys ----
        for (int kb = 0; kb < 8; kb++) {
            const int buf = kb & 1;
            if (kb < 7) {
                load_kv(Kh, Kl, kb + 1, buf ^ 1, h);
                CP_COMMIT();
                CP_WAIT(1);
            } else {
                CP_WAIT(0);
            }
            __syncthreads();

            const uint32_t kbh = smb + OFF_KV + buf * KVBUF;
            const uint32_t kbl = kbh + KVPART;
            float acc[2][4];
            #pragma unroll
            for (int nt = 0; nt < 2; nt++)
                #pragma unroll
                for (int e = 0; e < 4; e++) acc[nt][e] = 0.f;

            #pragma unroll
            for (int ks = 0; ks < 4; ks++) {
                uint32_t a_h[4], a_l[4];
                const uint32_t qoff =
                    (uint32_t)((wm * 16 + (lane & 15)) * STR
                               + ks * 16 + (lane >> 4) * 8) * 2;
                LDSM4(a_h, smb + OFF_Q + qoff);
                LDSM4(a_l, smb + OFF_Q + 4608 + qoff);
                #pragma unroll
                for (int nt = 0; nt < 2; nt++) {
                    uint32_t b_h[2], b_l[2];
                    const uint32_t koff =
                        (uint32_t)((wg * 16 + nt * 8 + (lane & 7)) * STR
                                   + ks * 16 + ((lane >> 3) & 1) * 8) * 2;
                    LDSM2(b_h, kbh + koff);
                    LDSM2(b_l, kbl + koff);
                    MMA16816(acc[nt], a_h, b_h);
                    MMA16816(acc[nt], a_h, b_l);
                    MMA16816(acc[nt], a_l, b_h);
                }
            }
            // mask + store logits
            const int r0 = wm * 16 + (lane >> 2);
            #pragma unroll
            for (int nt = 0; nt < 2; nt++) {
                const int c0 = kb * 128 + wg * 16 + nt * 8 + (lane & 3) * 2;
                const uint32_t w0 = s_mb[r0 * 32 + (c0 >> 5)];
                const uint32_t w1 = s_mb[(r0 + 8) * 32 + (c0 >> 5)];
                const int sh = c0 & 31;
                float2 o0, o1;
                o0.x = acc[nt][0] + (((w0 >> sh) & 1) ? -1.0e9f : 0.f);
                o0.y = acc[nt][1] + (((w0 >> (sh + 1)) & 1) ? -1.0e9f : 0.f);
                o1.x = acc[nt][2] + (((w1 >> sh) & 1) ? -1.0e9f : 0.f);
                o1.y = acc[nt][3] + (((w1 >> (sh + 1)) & 1) ? -1.0e9f : 0.f);
                *(float2*)&s_log[r0 * LSTR + c0]       = o0;
                *(float2*)&s_log[(r0 + 8) * LSTR + c0] = o1;
            }
            __syncthreads();
        }

        // prefetch V chunk 0 (buf 0) — overlaps softmax
        load_kv(Vh, Vl, 0, 0, h);
        CP_COMMIT();

        // ---- softmax: warp w owns rows 2w, 2w+1; pack p hi/lo in place ----
        #pragma unroll
        for (int rr = 0; rr < 2; rr++) {
            const int r = wid * 2 + rr;
            float mx = -3.4e38f;
            #pragma unroll 8
            for (int j = 0; j < 32; j++)
                mx = fmaxf(mx, s_log[r * LSTR + lane + 32 * j]);
            #pragma unroll
            for (int off = 16; off > 0; off >>= 1)
                mx = fmaxf(mx, __shfl_xor_sync(0xFFFFFFFFu, mx, off));
            float ssum = 0.f;
            #pragma unroll 8
            for (int j = 0; j < 32; j++) {
                const int idx = r * LSTR + lane + 32 * j;
                float p = __expf(s_log[idx] - mx);
                ssum += p;
                unsigned short hb = __bfloat16_as_ushort(__float2bfloat16(p));
                float hf = __uint_as_float((uint32_t)hb << 16);
                unsigned short lb =
                    __bfloat16_as_ushort(__float2bfloat16(p - hf));
                s_p[idx] = (uint32_t)hb | ((uint32_t)lb << 16);
            }
            #pragma unroll
            for (int off = 16; off > 0; off >>= 1)
                ssum += __shfl_xor_sync(0xFFFFFFFFu, ssum, off);
            if (lane == 0) s_inv[r] = 1.f / ssum;
        }
        __syncthreads();

        // ---- amean accumulation ----
        #pragma unroll 8
        for (int i = 0; i < 64; i++) {
            const int linear = i * 512 + tid;
            const int r = linear >> 10, c = linear & 1023;
            const uint32_t w = s_p[r * LSTR + c];
            float p = __uint_as_float(w << 16) +
                      __uint_as_float(w & 0xFFFF0000u);
            mean_acc[i] += p * s_inv[r];
        }

        // ---- P @ V over 8 chunks of 128 keys ----
        float cacc[4];
        #pragma unroll
        for (int e = 0; e < 4; e++) cacc[e] = 0.f;

        for (int kv = 0; kv < 8; kv++) {
            const int buf = kv & 1;
            if (kv < 7) {
                load_kv(Vh, Vl, kv + 1, buf ^ 1, h);
                CP_COMMIT();
                CP_WAIT(1);
            } else {
                CP_WAIT(0);
            }
            __syncthreads();

            const uint32_t vbh = smb + OFF_KV + buf * KVBUF;
            const uint32_t vbl = vbh + KVPART;
            const int r0 = wm * 16 + (lane >> 2);
            const int r1 = r0 + 8;

            #pragma unroll
            for (int ks = 0; ks < 8; ks++) {
                const int kk = kv * 128 + ks * 16 + (lane & 3) * 2;
                uint2 v00 = *(uint2*)&s_p[r0 * LSTR + kk];
                uint2 v02 = *(uint2*)&s_p[r0 * LSTR + kk + 8];
                uint2 v10 = *(uint2*)&s_p[r1 * LSTR + kk];
                uint2 v12 = *(uint2*)&s_p[r1 * LSTR + kk + 8];
                uint32_t a_h[4], a_l[4];
                a_h[0] = __byte_perm(v00.x, v00.y, 0x5410);
                a_l[0] = __byte_perm(v00.x, v00.y, 0x7632);
                a_h[1] = __byte_perm(v10.x, v10.y, 0x5410);
                a_l[1] = __byte_perm(v10.x, v10.y, 0x7632);
                a_h[2] = __byte_perm(v02.x, v02.y, 0x5410);
                a_l[2] = __byte_perm(v02.x, v02.y, 0x7632);
                a_h[3] = __byte_perm(v12.x, v12.y, 0x5410);
                a_l[3] = __byte_perm(v12.x, v12.y, 0x7632);

                uint32_t b_h[2], b_l[2];
                const uint32_t voff =
                    (uint32_t)((ks * 16 + (lane & 15)) * STR + wg * 8) * 2;
                LDSM2T(b_h, vbh + voff);
                LDSM2T(b_l, vbl + voff);

                MMA16816(cacc, a_h, b_h);
                MMA16816(cacc, a_h, b_l);
                MMA16816(cacc, a_l, b_h);
            }
            __syncthreads();
        }

        // ---- write ctx (normalized) ----
        {
            const int r0 = wm * 16 + (lane >> 2);
            const float inv0 = s_inv[r0];
            const float inv1 = s_inv[r0 + 8];
            const int col = h * 64 + wg * 8 + (lane & 3) * 2;
            float2 o0, o1;
            o0.x = cacc[0] * inv0; o0.y = cacc[1] * inv0;
            o1.x = cacc[2] * inv1; o1.y = cacc[3] * inv1;
            *(float2*)&Ctx[(tokbase + q0 + r0) * 1024 + col]     = o0;
            *(float2*)&Ctx[(tokbase + q0 + r0 + 8) * 1024 + col] = o1;
        }
        __syncthreads();
    }

    // ---- write attn mean ----
    float* aout = amean + (tokbase + q0) * LL;
    #pragma unroll 8
    for (int i = 0; i < 64; i++)
        aout[i * 512 + tid] = mean_acc[i] * (1.f / 16.f);
}

// ---------------------------------------------------------------------------
extern "C" void kernel_launch(void* const* d_in, const int* in_sizes, int n_in,
                              void* d_out, int out_size)
{
    const float* q    = (const float*)d_in[0];
    const float* k    = (const float*)d_in[1];
    const float* v    = (const float*)d_in[2];
    const float* mask = (const float*)d_in[3];
    const float* wq   = (const float*)d_in[4];
    const float* bq   = (const float*)d_in[5];
    const float* wk   = (const float*)d_in[6];
    const float* bk   = (const float*)d_in[7];
    const float* wv   = (const float*)d_in[8];
    const float* bv   = (const float*)d_in[9];
    const float* wo   = (const float*)d_in[10];
    const float* bo   = (const float*)d_in[11];

    float* out   = (float*)d_out;
    float* amean = out + (size_t)NTOK * DD;

    float *ctx;
    __nv_bfloat16 *ah, *al, *wh, *wl, *qh, *ql, *kh, *kl, *vh, *vl;
    cudaGetSymbolAddress((void**)&ctx, g_ctx);
    cudaGetSymbolAddress((void**)&ah,  g_ah);
    cudaGetSymbolAddress((void**)&al,  g_al);
    cudaGetSymbolAddress((void**)&wh,  g_wh);
    cudaGetSymbolAddress((void**)&wl,  g_wl);
    cudaGetSymbolAddress((void**)&qh,  g_qh);
    cudaGetSymbolAddress((void**)&ql,  g_ql);
    cudaGetSymbolAddress((void**)&kh,  g_kh);
    cudaGetSymbolAddress((void**)&kl,  g_kl);
    cudaGetSymbolAddress((void**)&vh,  g_vh);
    cudaGetSymbolAddress((void**)&vl,  g_vl);

    static int attr_set = 0;
    if (!attr_set) {
        cudaFuncSetAttribute(gemm_mma,
                             cudaFuncAttributeMaxDynamicSharedMemorySize,
                             GEMM_SMEM_BYTES);
        cudaFuncSetAttribute(attn_tc,
                             cudaFuncAttributeMaxDynamicSharedMemorySize,
                             AT_SMEM);
        attr_set = 1;
    }

    const dim3 gemm_grid(8, 128);
    const dim3 wt_grid(32, 32);
    const int  conv_blocks = (NTOK * DD) / (256 * 4);

    // Q projection -> bf16 hi/lo, pre-scaled by 1/sqrt(depth)=0.125
    conv_wt<<<wt_grid, 256>>>(wq, wh, wl);
    conv_split<<<conv_blocks, 256>>>(q, ah, al);
    gemm_mma<<<gemm_grid, 256, GEMM_SMEM_BYTES>>>(ah, al, wh, wl, bq,
                                                  nullptr, qh, ql, 1, 0.125f);
    // K projection
    conv_wt<<<wt_grid, 256>>>(wk, wh, wl);
    conv_split<<<conv_blocks, 256>>>(k, ah, al);
    gemm_mma<<<gemm_grid, 256, GEMM_SMEM_BYTES>>>(ah, al, wh, wl, bk,
                                                  nullptr, kh, kl, 1, 1.0f);
    // V projection
    conv_wt<<<wt_grid, 256>>>(wv, wh, wl);
    conv_split<<<conv_blocks, 256>>>(v, ah, al);
    gemm_mma<<<gemm_grid, 256, GEMM_SMEM_BYTES>>>(ah, al, wh, wl, bv,
                                                  nullptr, vh, vl, 1, 1.0f);

    // Tensor-core attention
    dim3 attn_grid(LL / 32, BS);
    attn_tc<<<attn_grid, 512, AT_SMEM>>>(qh, ql, kh, kl, vh, vl,
                                         mask, ctx, amean);

    // Output projection (fp32 out)
    conv_wt<<<wt_grid, 256>>>(wo, wh, wl);
    conv_split<<<conv_blocks, 256>>>(ctx, ah, al);
    gemm_mma<<<gemm_grid, 256, GEMM_SMEM_BYTES>>>(ah, al, wh, wl, bo,
                                                  out, nullptr, nullptr,
                                                  0, 1.0f);
}